// round 13
// baseline (speedup 1.0000x reference)
#include <cuda_runtime.h>
#include <math.h>

#define NVERT 200000
#define NEDGE 1200000
#define CG_ITERS 30
#define KS_NEG (-1000.0f)
#define H2_F 1.0e-4f
#define EPS_F 1.0e-8f
#define CH ((NVERT + 255) / 256)   // per-thread chunk for the 1-block scan

// ---------------- scratch (device globals; allocation is forbidden) ----------------
__device__ float4 g_p[NVERT];          // search direction
__device__ float4 g_r[NVERT];          // residual
__device__ float4 g_x[NVERT];          // solution
__device__ float4 g_ap[NVERT];         // Ap
__device__ float4 g_f[NEDGE];          // per-edge f_e
__device__ float4 g_J1[NEDGE];         // Jxx Jxy Jxz Jyy
__device__ float2 g_J2[NEDGE];         // Jyz Jzz
__device__ int    g_degA[NVERT], g_degB[NVERT];
__device__ int    g_offA[NVERT + 1], g_offB[NVERT + 1];
__device__ int    g_curA[NVERT], g_curB[NVERT];
__device__ int    g_lstA[NEDGE], g_lstB[NEDGE];
__device__ float  g_rs[CG_ITERS + 1];   // f32 scalars, matching reference precision
__device__ float  g_pAp[CG_ITERS];

// ---------------- CSR build (deterministic; integer structure only) --------------
__global__ __launch_bounds__(256) void k_zero_deg() {
    int i = blockIdx.x * 256 + threadIdx.x;
    if (i < NVERT) { g_degA[i] = 0; g_degB[i] = 0; }
}

__global__ __launch_bounds__(256) void k_count(const int2* __restrict__ edges) {
    int i = blockIdx.x * 256 + threadIdx.x;
    if (i >= NEDGE) return;
    int2 e = edges[i];
    atomicAdd(&g_degA[e.x], 1);
    atomicAdd(&g_degB[e.y], 1);
}

__global__ void k_scan() {
    __shared__ int sA[256], sB[256];
    int t = threadIdx.x;
    int lo = t * CH;
    int hi = lo + CH; if (hi > NVERT) hi = NVERT;
    int a = 0, b = 0;
    for (int v = lo; v < hi; ++v) { a += g_degA[v]; b += g_degB[v]; }
    sA[t] = a; sB[t] = b;
    __syncthreads();
    if (t == 0) {
        int ra = 0, rb = 0;
        for (int i = 0; i < 256; ++i) {
            int ta = sA[i]; sA[i] = ra; ra += ta;
            int tb = sB[i]; sB[i] = rb; rb += tb;
        }
    }
    __syncthreads();
    int ra = sA[t], rb = sB[t];
    for (int v = lo; v < hi; ++v) {
        g_offA[v] = ra; ra += g_degA[v];
        g_offB[v] = rb; rb += g_degB[v];
    }
    if (t == 255) { g_offA[NVERT] = ra; g_offB[NVERT] = rb; }
}

__global__ __launch_bounds__(256) void k_copycur() {
    int i = blockIdx.x * 256 + threadIdx.x;
    if (i < NVERT) { g_curA[i] = g_offA[i]; g_curB[i] = g_offB[i]; }
}

__global__ __launch_bounds__(256) void k_fill(const int2* __restrict__ edges) {
    int i = blockIdx.x * 256 + threadIdx.x;
    if (i >= NEDGE) return;
    int2 e = edges[i];
    g_lstA[atomicAdd(&g_curA[e.x], 1)] = i;
    g_lstB[atomicAdd(&g_curB[e.y], 1)] = i;
}

// sort each vertex's incident lists ascending by edge id -> sequential-scatter order
__global__ __launch_bounds__(256) void k_sort() {
    int v = blockIdx.x * 256 + threadIdx.x;
    if (v >= NVERT) return;
    {
        int lo = g_offA[v], hi = g_offA[v + 1];
        for (int i = lo + 1; i < hi; ++i) {
            int key = g_lstA[i];
            int j = i - 1;
            while (j >= lo && g_lstA[j] > key) { g_lstA[j + 1] = g_lstA[j]; --j; }
            g_lstA[j + 1] = key;
        }
    }
    {
        int lo = g_offB[v], hi = g_offB[v + 1];
        for (int i = lo + 1; i < hi; ++i) {
            int key = g_lstB[i];
            int j = i - 1;
            while (j >= lo && g_lstB[j] > key) { g_lstB[j + 1] = g_lstB[j]; --j; }
            g_lstB[j + 1] = key;
        }
    }
}

// ---------------- Jacobian: exact replica of reference f32 arithmetic -------------
__global__ __launch_bounds__(256) void k_params(const float* __restrict__ pos,
                                                const float* __restrict__ rest,
                                                const int2*  __restrict__ edges) {
    int i = blockIdx.x * 256 + threadIdx.x;
    if (i >= NEDGE) return;
    int2 e = edges[i];
    float dx = __fsub_rn(pos[3 * e.x + 0], pos[3 * e.y + 0]);
    float dy = __fsub_rn(pos[3 * e.x + 1], pos[3 * e.y + 1]);
    float dz = __fsub_rn(pos[3 * e.x + 2], pos[3 * e.y + 2]);
    float s  = __fadd_rn(__fadd_rn(__fmul_rn(dx, dx), __fmul_rn(dy, dy)), __fmul_rn(dz, dz));
    float l  = __fadd_rn(__fsqrt_rn(s), EPS_F);
    float hx = __fdiv_rn(dx, l);
    float hy = __fdiv_rn(dy, l);
    float hz = __fdiv_rn(dz, l);
    float coef = __fsub_rn(1.0f, __fdiv_rn(rest[i], l));
    float xx = __fmul_rn(hx, hx), xy = __fmul_rn(hx, hy), xz = __fmul_rn(hx, hz);
    float yy = __fmul_rn(hy, hy), yz = __fmul_rn(hy, hz), zz = __fmul_rn(hz, hz);
    float Jxx = __fmul_rn(KS_NEG, __fadd_rn(__fmul_rn(coef, __fsub_rn(1.0f, xx)), xx));
    float Jxy = __fmul_rn(KS_NEG, __fadd_rn(__fmul_rn(coef, __fsub_rn(0.0f, xy)), xy));
    float Jxz = __fmul_rn(KS_NEG, __fadd_rn(__fmul_rn(coef, __fsub_rn(0.0f, xz)), xz));
    float Jyy = __fmul_rn(KS_NEG, __fadd_rn(__fmul_rn(coef, __fsub_rn(1.0f, yy)), yy));
    float Jyz = __fmul_rn(KS_NEG, __fadd_rn(__fmul_rn(coef, __fsub_rn(0.0f, yz)), yz));
    float Jzz = __fmul_rn(KS_NEG, __fadd_rn(__fmul_rn(coef, __fsub_rn(1.0f, zz)), zz));
    g_J1[i] = make_float4(Jxx, Jxy, Jxz, Jyy);
    g_J2[i] = make_float2(Jyz, Jzz);
}

__global__ __launch_bounds__(256) void k_init(const float* __restrict__ rhs) {
    int i = blockIdx.x * 256 + threadIdx.x;
    if (i >= NVERT) return;
    float4 v = make_float4(rhs[3 * i + 0], rhs[3 * i + 1], rhs[3 * i + 2], 0.0f);
    g_p[i] = v;
    g_r[i] = v;
    g_x[i] = make_float4(0.0f, 0.0f, 0.0f, 0.0f);
}

// ---------------- CG iteration --------------------------------------------------
// 1) f_e = J_e * (p[e0]-p[e1]);  row dot = (J0*d0 + J1*d1) + J2*d2, no FMA
__global__ __launch_bounds__(256) void k_force(const int2* __restrict__ edges) {
    int i = blockIdx.x * 256 + threadIdx.x;
    if (i >= NEDGE) return;
    int2 e = edges[i];
    float4 p0 = g_p[e.x];
    float4 p1 = g_p[e.y];
    float dvx = __fsub_rn(p0.x, p1.x);
    float dvy = __fsub_rn(p0.y, p1.y);
    float dvz = __fsub_rn(p0.z, p1.z);
    float4 J1 = g_J1[i];
    float2 J2 = g_J2[i];
    float fx = __fadd_rn(__fadd_rn(__fmul_rn(J1.x, dvx), __fmul_rn(J1.y, dvy)), __fmul_rn(J1.z, dvz));
    float fy = __fadd_rn(__fadd_rn(__fmul_rn(J1.y, dvx), __fmul_rn(J1.w, dvy)), __fmul_rn(J2.x, dvz));
    float fz = __fadd_rn(__fadd_rn(__fmul_rn(J1.z, dvx), __fmul_rn(J2.x, dvy)), __fmul_rn(J2.y, dvz));
    g_f[i] = make_float4(fx, fy, fz, 0.0f);
}

// 2) gather in sequential-scatter order (all e0 adds asc, then all e1 subs asc);
//    Ap = m*p - H2*Jv
__global__ __launch_bounds__(256) void k_gather(const float* __restrict__ mass) {
    int v = blockIdx.x * 256 + threadIdx.x;
    if (v >= NVERT) return;
    float jx = 0.0f, jy = 0.0f, jz = 0.0f;
    int lo = g_offA[v], hi = g_offA[v + 1];
    for (int j = lo; j < hi; ++j) {
        float4 f = g_f[g_lstA[j]];
        jx = __fadd_rn(jx, f.x);
        jy = __fadd_rn(jy, f.y);
        jz = __fadd_rn(jz, f.z);
    }
    lo = g_offB[v]; hi = g_offB[v + 1];
    for (int j = lo; j < hi; ++j) {
        float4 f = g_f[g_lstB[j]];
        jx = __fsub_rn(jx, f.x);
        jy = __fsub_rn(jy, f.y);
        jz = __fsub_rn(jz, f.z);
    }
    float4 p = g_p[v];
    float  m = mass[v];
    float apx = __fsub_rn(__fmul_rn(m, p.x), __fmul_rn(H2_F, jx));
    float apy = __fsub_rn(__fmul_rn(m, p.y), __fmul_rn(H2_F, jy));
    float apz = __fsub_rn(__fmul_rn(m, p.z), __fmul_rn(H2_F, jz));
    g_ap[v] = make_float4(apx, apy, apz, 0.0f);
}

// sequential f32 dot, bit-identical fold order (v ascending; x,y,z per vertex),
// producer/consumer pipelined with large chunks to amortize barriers:
// threads 32..191 stage A, threads 192..351 stage B (double-buffered smem);
// thread 0 runs the dependent FADD chain. 200000/160 = 1250 chunks exactly.
#define DOT_CHUNK 160
#define DOT_NCH   (NVERT / DOT_CHUNK)
__global__ __launch_bounds__(384) void k_sdot(const float4* __restrict__ A,
                                              const float4* __restrict__ B,
                                              float* __restrict__ out) {
    __shared__ float4 sa[2][DOT_CHUNK], sb[2][DOT_CHUNK];
    int tid = threadIdx.x;
    int la = tid - 32;     // 0..159 for A stagers
    int lb = tid - 192;    // 0..159 for B stagers
    bool isA = (tid >= 32  && tid < 192);
    bool isB = (tid >= 192 && tid < 352);
    // prologue: fill buffer 0 with chunk 0
    if (isA) sa[0][la] = A[la];
    if (isB) sb[0][lb] = B[lb];
    __syncthreads();
    float acc = 0.0f;
    for (int c = 0; c < DOT_NCH; ++c) {
        int cb = c & 1, nb = cb ^ 1;
        if (c + 1 < DOT_NCH) {
            int base = (c + 1) * DOT_CHUNK;
            if (isA) sa[nb][la] = A[base + la];
            if (isB) sb[nb][lb] = B[base + lb];
        }
        if (tid == 0) {
            #pragma unroll 8
            for (int j = 0; j < DOT_CHUNK; ++j) {
                float4 a = sa[cb][j];
                float4 b = sb[cb][j];
                acc = __fadd_rn(acc, __fmul_rn(a.x, b.x));
                acc = __fadd_rn(acc, __fmul_rn(a.y, b.y));
                acc = __fadd_rn(acc, __fmul_rn(a.z, b.z));
            }
        }
        __syncthreads();
    }
    if (tid == 0) *out = acc;
}

// 3) alpha = rs/(pAp+EPS); x += a p; r -= a Ap; emit x on last iteration
__global__ __launch_bounds__(256) void k_update(float* __restrict__ out, int k, int last) {
    int v = blockIdx.x * 256 + threadIdx.x;
    if (v >= NVERT) return;
    float alpha = __fdiv_rn(g_rs[k], __fadd_rn(g_pAp[k], EPS_F));
    float4 p  = g_p[v];
    float4 ap = g_ap[v];
    float4 x  = g_x[v];
    float4 r  = g_r[v];
    x.x = __fadd_rn(x.x, __fmul_rn(alpha, p.x));
    x.y = __fadd_rn(x.y, __fmul_rn(alpha, p.y));
    x.z = __fadd_rn(x.z, __fmul_rn(alpha, p.z));
    r.x = __fsub_rn(r.x, __fmul_rn(alpha, ap.x));
    r.y = __fsub_rn(r.y, __fmul_rn(alpha, ap.y));
    r.z = __fsub_rn(r.z, __fmul_rn(alpha, ap.z));
    g_x[v] = x;
    g_r[v] = r;
    if (last) {
        out[3 * v + 0] = x.x;
        out[3 * v + 1] = x.y;
        out[3 * v + 2] = x.z;
    }
}

// 4) beta = rs_{k+1}/(rs_k+EPS); p = r + beta p
__global__ __launch_bounds__(256) void k_pupdate(int k) {
    int v = blockIdx.x * 256 + threadIdx.x;
    if (v >= NVERT) return;
    float beta = __fdiv_rn(g_rs[k + 1], __fadd_rn(g_rs[k], EPS_F));
    float4 r = g_r[v];
    float4 p = g_p[v];
    p.x = __fadd_rn(r.x, __fmul_rn(beta, p.x));
    p.y = __fadd_rn(r.y, __fmul_rn(beta, p.y));
    p.z = __fadd_rn(r.z, __fmul_rn(beta, p.z));
    p.w = 0.0f;
    g_p[v] = p;
}

// ---------------- launch ----------------
extern "C" void kernel_launch(void* const* d_in, const int* in_sizes, int n_in,
                              void* d_out, int out_size) {
    // setup_inputs() dict order {rhs, pos, mass, rest_len, edges}
    const float* rhs  = (const float*)d_in[0];
    const float* pos  = (const float*)d_in[1];
    const float* mass = (const float*)d_in[2];
    const float* rest = (const float*)d_in[3];
    const int2*  edges = (const int2*)d_in[4];
    // defensive: alphabetical order {edges, mass, pos, rest_len, rhs}
    if (n_in == 5 && in_sizes[0] == 2 * NEDGE) {
        edges = (const int2*)d_in[0];
        mass  = (const float*)d_in[1];
        pos   = (const float*)d_in[2];
        rest  = (const float*)d_in[3];
        rhs   = (const float*)d_in[4];
    }
    float* x = (float*)d_out;

    const int EB = (NEDGE + 255) / 256;
    const int VB = (NVERT + 255) / 256;

    // pointers to device-global scalar slots
    float* rs_ptr  = nullptr;
    float* pap_ptr = nullptr;
    cudaGetSymbolAddress((void**)&rs_ptr,  g_rs);
    cudaGetSymbolAddress((void**)&pap_ptr, g_pAp);

    float4* p_ptr  = nullptr;
    float4* r_ptr  = nullptr;
    float4* ap_ptr = nullptr;
    cudaGetSymbolAddress((void**)&p_ptr,  g_p);
    cudaGetSymbolAddress((void**)&r_ptr,  g_r);
    cudaGetSymbolAddress((void**)&ap_ptr, g_ap);

    k_zero_deg<<<VB, 256>>>();
    k_count<<<EB, 256>>>(edges);
    k_scan<<<1, 256>>>();
    k_copycur<<<VB, 256>>>();
    k_fill<<<EB, 256>>>(edges);
    k_sort<<<VB, 256>>>();
    k_params<<<EB, 256>>>(pos, rest, edges);
    k_init<<<VB, 256>>>(rhs);
    k_sdot<<<1, 384>>>(r_ptr, r_ptr, rs_ptr + 0);   // rs0 = vdot(b,b)

    for (int k = 0; k < CG_ITERS; ++k) {
        k_force<<<EB, 256>>>(edges);
        k_gather<<<VB, 256>>>(mass);
        k_sdot<<<1, 384>>>(p_ptr, ap_ptr, pap_ptr + k);       // pAp_k (sequential f32)
        k_update<<<VB, 256>>>(x, k, (k == CG_ITERS - 1) ? 1 : 0);
        k_sdot<<<1, 384>>>(r_ptr, r_ptr, rs_ptr + k + 1);     // rs_{k+1} (sequential f32)
        if (k < CG_ITERS - 1) k_pupdate<<<VB, 256>>>(k);
    }
}

// round 15
// speedup vs baseline: 1.5574x; 1.5574x over previous
#include <cuda_runtime.h>
#include <math.h>

#define NVERT 200000
#define NEDGE 1200000
#define CG_ITERS 30
#define KS_NEG (-1000.0f)
#define H2_F 1.0e-4f
#define EPS_F 1.0e-8f
#define CH ((NVERT + 255) / 256)   // per-thread chunk for the 1-block scan

// ---------------- scratch (device globals; allocation is forbidden) ----------------
__device__ float4 g_p[NVERT];          // search direction
__device__ float4 g_r[NVERT];          // residual
__device__ float4 g_x[NVERT];          // solution
__device__ float4 g_ap[NVERT];         // Ap
__device__ float4 g_f[NEDGE];          // per-edge f_e
__device__ float4 g_J1[NEDGE];         // Jxx Jxy Jxz Jyy
__device__ float2 g_J2[NEDGE];         // Jyz Jzz
__device__ int    g_degA[NVERT], g_degB[NVERT];
__device__ int    g_offA[NVERT + 1], g_offB[NVERT + 1];
__device__ int    g_curA[NVERT], g_curB[NVERT];
__device__ int    g_lstA[NEDGE], g_lstB[NEDGE];
__device__ float  g_rs[CG_ITERS + 1];   // f32 scalars, matching reference precision
__device__ float  g_pAp[CG_ITERS];

// ---------------- CSR build (deterministic; integer structure only) --------------
__global__ __launch_bounds__(256) void k_zero_deg() {
    int i = blockIdx.x * 256 + threadIdx.x;
    if (i < NVERT) { g_degA[i] = 0; g_degB[i] = 0; }
}

__global__ __launch_bounds__(256) void k_count(const int2* __restrict__ edges) {
    int i = blockIdx.x * 256 + threadIdx.x;
    if (i >= NEDGE) return;
    int2 e = edges[i];
    atomicAdd(&g_degA[e.x], 1);
    atomicAdd(&g_degB[e.y], 1);
}

__global__ void k_scan() {
    __shared__ int sA[256], sB[256];
    int t = threadIdx.x;
    int lo = t * CH;
    int hi = lo + CH; if (hi > NVERT) hi = NVERT;
    int a = 0, b = 0;
    for (int v = lo; v < hi; ++v) { a += g_degA[v]; b += g_degB[v]; }
    sA[t] = a; sB[t] = b;
    __syncthreads();
    if (t == 0) {
        int ra = 0, rb = 0;
        for (int i = 0; i < 256; ++i) {
            int ta = sA[i]; sA[i] = ra; ra += ta;
            int tb = sB[i]; sB[i] = rb; rb += tb;
        }
    }
    __syncthreads();
    int ra = sA[t], rb = sB[t];
    for (int v = lo; v < hi; ++v) {
        g_offA[v] = ra; ra += g_degA[v];
        g_offB[v] = rb; rb += g_degB[v];
    }
    if (t == 255) { g_offA[NVERT] = ra; g_offB[NVERT] = rb; }
}

__global__ __launch_bounds__(256) void k_copycur() {
    int i = blockIdx.x * 256 + threadIdx.x;
    if (i < NVERT) { g_curA[i] = g_offA[i]; g_curB[i] = g_offB[i]; }
}

__global__ __launch_bounds__(256) void k_fill(const int2* __restrict__ edges) {
    int i = blockIdx.x * 256 + threadIdx.x;
    if (i >= NEDGE) return;
    int2 e = edges[i];
    g_lstA[atomicAdd(&g_curA[e.x], 1)] = i;
    g_lstB[atomicAdd(&g_curB[e.y], 1)] = i;
}

// sort each vertex's incident lists ascending by edge id -> sequential-scatter order
__global__ __launch_bounds__(256) void k_sort() {
    int v = blockIdx.x * 256 + threadIdx.x;
    if (v >= NVERT) return;
    {
        int lo = g_offA[v], hi = g_offA[v + 1];
        for (int i = lo + 1; i < hi; ++i) {
            int key = g_lstA[i];
            int j = i - 1;
            while (j >= lo && g_lstA[j] > key) { g_lstA[j + 1] = g_lstA[j]; --j; }
            g_lstA[j + 1] = key;
        }
    }
    {
        int lo = g_offB[v], hi = g_offB[v + 1];
        for (int i = lo + 1; i < hi; ++i) {
            int key = g_lstB[i];
            int j = i - 1;
            while (j >= lo && g_lstB[j] > key) { g_lstB[j + 1] = g_lstB[j]; --j; }
            g_lstB[j + 1] = key;
        }
    }
}

// ---------------- Jacobian: exact replica of reference f32 arithmetic -------------
__global__ __launch_bounds__(256) void k_params(const float* __restrict__ pos,
                                                const float* __restrict__ rest,
                                                const int2*  __restrict__ edges) {
    int i = blockIdx.x * 256 + threadIdx.x;
    if (i >= NEDGE) return;
    int2 e = edges[i];
    float dx = __fsub_rn(pos[3 * e.x + 0], pos[3 * e.y + 0]);
    float dy = __fsub_rn(pos[3 * e.x + 1], pos[3 * e.y + 1]);
    float dz = __fsub_rn(pos[3 * e.x + 2], pos[3 * e.y + 2]);
    float s  = __fadd_rn(__fadd_rn(__fmul_rn(dx, dx), __fmul_rn(dy, dy)), __fmul_rn(dz, dz));
    float l  = __fadd_rn(__fsqrt_rn(s), EPS_F);
    float hx = __fdiv_rn(dx, l);
    float hy = __fdiv_rn(dy, l);
    float hz = __fdiv_rn(dz, l);
    float coef = __fsub_rn(1.0f, __fdiv_rn(rest[i], l));
    float xx = __fmul_rn(hx, hx), xy = __fmul_rn(hx, hy), xz = __fmul_rn(hx, hz);
    float yy = __fmul_rn(hy, hy), yz = __fmul_rn(hy, hz), zz = __fmul_rn(hz, hz);
    float Jxx = __fmul_rn(KS_NEG, __fadd_rn(__fmul_rn(coef, __fsub_rn(1.0f, xx)), xx));
    float Jxy = __fmul_rn(KS_NEG, __fadd_rn(__fmul_rn(coef, __fsub_rn(0.0f, xy)), xy));
    float Jxz = __fmul_rn(KS_NEG, __fadd_rn(__fmul_rn(coef, __fsub_rn(0.0f, xz)), xz));
    float Jyy = __fmul_rn(KS_NEG, __fadd_rn(__fmul_rn(coef, __fsub_rn(1.0f, yy)), yy));
    float Jyz = __fmul_rn(KS_NEG, __fadd_rn(__fmul_rn(coef, __fsub_rn(0.0f, yz)), yz));
    float Jzz = __fmul_rn(KS_NEG, __fadd_rn(__fmul_rn(coef, __fsub_rn(1.0f, zz)), zz));
    g_J1[i] = make_float4(Jxx, Jxy, Jxz, Jyy);
    g_J2[i] = make_float2(Jyz, Jzz);
}

__global__ __launch_bounds__(256) void k_init(const float* __restrict__ rhs) {
    int i = blockIdx.x * 256 + threadIdx.x;
    if (i >= NVERT) return;
    float4 v = make_float4(rhs[3 * i + 0], rhs[3 * i + 1], rhs[3 * i + 2], 0.0f);
    g_p[i] = v;
    g_r[i] = v;
    g_x[i] = make_float4(0.0f, 0.0f, 0.0f, 0.0f);
}

// ---------------- CG iteration --------------------------------------------------
// 1) f_e = J_e * (p[e0]-p[e1]);  row dot = (J0*d0 + J1*d1) + J2*d2, no FMA
__global__ __launch_bounds__(256) void k_force(const int2* __restrict__ edges) {
    int i = blockIdx.x * 256 + threadIdx.x;
    if (i >= NEDGE) return;
    int2 e = edges[i];
    float4 p0 = g_p[e.x];
    float4 p1 = g_p[e.y];
    float dvx = __fsub_rn(p0.x, p1.x);
    float dvy = __fsub_rn(p0.y, p1.y);
    float dvz = __fsub_rn(p0.z, p1.z);
    float4 J1 = g_J1[i];
    float2 J2 = g_J2[i];
    float fx = __fadd_rn(__fadd_rn(__fmul_rn(J1.x, dvx), __fmul_rn(J1.y, dvy)), __fmul_rn(J1.z, dvz));
    float fy = __fadd_rn(__fadd_rn(__fmul_rn(J1.y, dvx), __fmul_rn(J1.w, dvy)), __fmul_rn(J2.x, dvz));
    float fz = __fadd_rn(__fadd_rn(__fmul_rn(J1.z, dvx), __fmul_rn(J2.x, dvy)), __fmul_rn(J2.y, dvz));
    g_f[i] = make_float4(fx, fy, fz, 0.0f);
}

// 2) gather in sequential-scatter order (all e0 adds asc, then all e1 subs asc);
//    Ap = m*p - H2*Jv
__global__ __launch_bounds__(256) void k_gather(const float* __restrict__ mass) {
    int v = blockIdx.x * 256 + threadIdx.x;
    if (v >= NVERT) return;
    float jx = 0.0f, jy = 0.0f, jz = 0.0f;
    int lo = g_offA[v], hi = g_offA[v + 1];
    for (int j = lo; j < hi; ++j) {
        float4 f = g_f[g_lstA[j]];
        jx = __fadd_rn(jx, f.x);
        jy = __fadd_rn(jy, f.y);
        jz = __fadd_rn(jz, f.z);
    }
    lo = g_offB[v]; hi = g_offB[v + 1];
    for (int j = lo; j < hi; ++j) {
        float4 f = g_f[g_lstB[j]];
        jx = __fsub_rn(jx, f.x);
        jy = __fsub_rn(jy, f.y);
        jz = __fsub_rn(jz, f.z);
    }
    float4 p = g_p[v];
    float  m = mass[v];
    float apx = __fsub_rn(__fmul_rn(m, p.x), __fmul_rn(H2_F, jx));
    float apy = __fsub_rn(__fmul_rn(m, p.y), __fmul_rn(H2_F, jy));
    float apz = __fsub_rn(__fmul_rn(m, p.z), __fmul_rn(H2_F, jz));
    g_ap[v] = make_float4(apx, apy, apz, 0.0f);
}

// sequential f32 dot, bit-identical fold order (flattened: v ascending; x,y,z).
// 480 stager threads (tids 32..511) each compute ONE product into double-buffered
// smem in flattened order; thread 0 folds 480 products per chunk as
// 120 x (LDS.128 + 4 dependent FADD) — minimal instruction stream on the chain.
// Product values are bit-identical (__fmul_rn), fold order identical.
#define DOT_CHUNK 160                    // vertices per chunk; 3*160=480 products
#define DOT_NCH   (NVERT / DOT_CHUNK)    // 1250 chunks exactly
__global__ __launch_bounds__(512) void k_sdot(const float* __restrict__ A,
                                              const float* __restrict__ B,
                                              float* __restrict__ out) {
    __shared__ float s[2][3 * DOT_CHUNK];   // 2 x 480 floats, 16B-aligned
    int tid = threadIdx.x;
    int q = tid - 32;                        // 0..479: product index within chunk
    int vq = q / 3, cq = q % 3;              // vertex-in-chunk, component
    bool stage = (tid >= 32);
    if (stage) {
        s[0][q] = __fmul_rn(A[4 * vq + cq], B[4 * vq + cq]);   // chunk 0
    }
    __syncthreads();
    float acc = 0.0f;
    for (int ch = 0; ch < DOT_NCH; ++ch) {
        int cb = ch & 1, nb = cb ^ 1;
        if (stage && ch + 1 < DOT_NCH) {
            int v = (ch + 1) * DOT_CHUNK + vq;
            s[nb][q] = __fmul_rn(A[4 * v + cq], B[4 * v + cq]);
        }
        if (tid == 0) {
            const float4* sp = (const float4*)s[cb];
            #pragma unroll
            for (int j = 0; j < (3 * DOT_CHUNK) / 4; ++j) {
                float4 t = sp[j];
                acc = __fadd_rn(acc, t.x);
                acc = __fadd_rn(acc, t.y);
                acc = __fadd_rn(acc, t.z);
                acc = __fadd_rn(acc, t.w);
            }
        }
        __syncthreads();
    }
    if (tid == 0) *out = acc;
}

// 3) alpha = rs/(pAp+EPS); x += a p; r -= a Ap; emit x on last iteration
__global__ __launch_bounds__(256) void k_update(float* __restrict__ out, int k, int last) {
    int v = blockIdx.x * 256 + threadIdx.x;
    if (v >= NVERT) return;
    float alpha = __fdiv_rn(g_rs[k], __fadd_rn(g_pAp[k], EPS_F));
    float4 p  = g_p[v];
    float4 ap = g_ap[v];
    float4 x  = g_x[v];
    float4 r  = g_r[v];
    x.x = __fadd_rn(x.x, __fmul_rn(alpha, p.x));
    x.y = __fadd_rn(x.y, __fmul_rn(alpha, p.y));
    x.z = __fadd_rn(x.z, __fmul_rn(alpha, p.z));
    r.x = __fsub_rn(r.x, __fmul_rn(alpha, ap.x));
    r.y = __fsub_rn(r.y, __fmul_rn(alpha, ap.y));
    r.z = __fsub_rn(r.z, __fmul_rn(alpha, ap.z));
    g_x[v] = x;
    g_r[v] = r;
    if (last) {
        out[3 * v + 0] = x.x;
        out[3 * v + 1] = x.y;
        out[3 * v + 2] = x.z;
    }
}

// 4) beta = rs_{k+1}/(rs_k+EPS); p = r + beta p
__global__ __launch_bounds__(256) void k_pupdate(int k) {
    int v = blockIdx.x * 256 + threadIdx.x;
    if (v >= NVERT) return;
    float beta = __fdiv_rn(g_rs[k + 1], __fadd_rn(g_rs[k], EPS_F));
    float4 r = g_r[v];
    float4 p = g_p[v];
    p.x = __fadd_rn(r.x, __fmul_rn(beta, p.x));
    p.y = __fadd_rn(r.y, __fmul_rn(beta, p.y));
    p.z = __fadd_rn(r.z, __fmul_rn(beta, p.z));
    p.w = 0.0f;
    g_p[v] = p;
}

// ---------------- launch ----------------
extern "C" void kernel_launch(void* const* d_in, const int* in_sizes, int n_in,
                              void* d_out, int out_size) {
    // setup_inputs() dict order {rhs, pos, mass, rest_len, edges}
    const float* rhs  = (const float*)d_in[0];
    const float* pos  = (const float*)d_in[1];
    const float* mass = (const float*)d_in[2];
    const float* rest = (const float*)d_in[3];
    const int2*  edges = (const int2*)d_in[4];
    // defensive: alphabetical order {edges, mass, pos, rest_len, rhs}
    if (n_in == 5 && in_sizes[0] == 2 * NEDGE) {
        edges = (const int2*)d_in[0];
        mass  = (const float*)d_in[1];
        pos   = (const float*)d_in[2];
        rest  = (const float*)d_in[3];
        rhs   = (const float*)d_in[4];
    }
    float* x = (float*)d_out;

    const int EB = (NEDGE + 255) / 256;
    const int VB = (NVERT + 255) / 256;

    // pointers to device-global scalar slots
    float* rs_ptr  = nullptr;
    float* pap_ptr = nullptr;
    cudaGetSymbolAddress((void**)&rs_ptr,  g_rs);
    cudaGetSymbolAddress((void**)&pap_ptr, g_pAp);

    float* p_ptr  = nullptr;
    float* r_ptr  = nullptr;
    float* ap_ptr = nullptr;
    cudaGetSymbolAddress((void**)&p_ptr,  g_p);
    cudaGetSymbolAddress((void**)&r_ptr,  g_r);
    cudaGetSymbolAddress((void**)&ap_ptr, g_ap);

    k_zero_deg<<<VB, 256>>>();
    k_count<<<EB, 256>>>(edges);
    k_scan<<<1, 256>>>();
    k_copycur<<<VB, 256>>>();
    k_fill<<<EB, 256>>>(edges);
    k_sort<<<VB, 256>>>();
    k_params<<<EB, 256>>>(pos, rest, edges);
    k_init<<<VB, 256>>>(rhs);
    k_sdot<<<1, 512>>>(r_ptr, r_ptr, rs_ptr + 0);   // rs0 = vdot(b,b)

    for (int k = 0; k < CG_ITERS; ++k) {
        k_force<<<EB, 256>>>(edges);
        k_gather<<<VB, 256>>>(mass);
        k_sdot<<<1, 512>>>(p_ptr, ap_ptr, pap_ptr + k);       // pAp_k (sequential f32)
        k_update<<<VB, 256>>>(x, k, (k == CG_ITERS - 1) ? 1 : 0);
        k_sdot<<<1, 512>>>(r_ptr, r_ptr, rs_ptr + k + 1);     // rs_{k+1} (sequential f32)
        if (k < CG_ITERS - 1) k_pupdate<<<VB, 256>>>(k);
    }
}